// round 11
// baseline (speedup 1.0000x reference)
#include <cuda_runtime.h>
#include <cuda_fp16.h>
#include <cstdint>

// KPConv warp-MMA GEMM: R6 pair-split structure, fp16 2-pass, ROWB=112, 5 CTAs.
//   A[p, j] = exp(-0.5*d2(p,k)/sigma^2) * x[p,i]  (j=3k+i, 48 cols = 3 k-tiles)
//   out = A @ W.  fp32 via fp16 A-split, W rounded once: D = Ah*Wh + Al*Wh.
// Pair of warps owns a 32-row group; each warp builds its 16-row A tile
// (hi/lo fp16, stride 112B, conflict-free), computes its 32-col n-half of BOTH
// tiles. Double-buffered A; one named bar.sync(64)/iter; x prefetched;
// kernel points hoisted to registers (keeps LDS off the exp critical path).

#define KP_    16
#define JDIM   48
#define COUT_  64
#define NTHR   128
#define ROWB   112
#define AWARP  (16 * ROWB)   // 1792 B per (warp, half)

__device__ __forceinline__ uint32_t smem_u32(const void* p) {
    uint32_t a;
    asm("{ .reg .u64 t; cvta.to.shared.u64 t, %1; cvt.u32.u64 %0, t; }" : "=r"(a) : "l"(p));
    return a;
}
__device__ __forceinline__ uint32_t pack_h_rn(float lo, float hi) {
    uint32_t r;
    asm("cvt.rn.f16x2.f32 %0, %1, %2;" : "=r"(r) : "f"(hi), "f"(lo));
    return r;
}
__device__ __forceinline__ void ldsm_x4(uint32_t* r, uint32_t addr) {
    asm volatile("ldmatrix.sync.aligned.m8n8.x4.shared.b16 {%0,%1,%2,%3}, [%4];"
                 : "=r"(r[0]), "=r"(r[1]), "=r"(r[2]), "=r"(r[3]) : "r"(addr));
}
__device__ __forceinline__ void mma_f16(float* c, const uint32_t* a, const uint32_t* b) {
    asm volatile(
        "mma.sync.aligned.m16n8k16.row.col.f32.f16.f16.f32 "
        "{%0,%1,%2,%3}, {%4,%5,%6,%7}, {%8,%9}, {%0,%1,%2,%3};"
        : "+f"(c[0]), "+f"(c[1]), "+f"(c[2]), "+f"(c[3])
        : "r"(a[0]), "r"(a[1]), "r"(a[2]), "r"(a[3]), "r"(b[0]), "r"(b[1]));
}
__device__ __forceinline__ float ex2f(float a) {
    float r;
    asm("ex2.approx.f32 %0, %1;" : "=f"(r) : "f"(a));
    return r;
}
__device__ __forceinline__ void bar_pair(int id) {
    asm volatile("bar.sync %0, 64;" :: "r"(id) : "memory");
}

__global__ __launch_bounds__(NTHR, 5)
void kpconv_f16q_kernel(const float* __restrict__ x,
                        const float* __restrict__ kpts,
                        const float* __restrict__ wts,
                        const float* __restrict__ sigma,
                        float* __restrict__ out,
                        int npts)
{
    // [buf][warp][hi/lo][16 rows x 112B] = 28672 B; W (12288B) staged aliased.
    __shared__ __align__(16) char sA[2][4][2][AWARP];
    __shared__ float sKP[JDIM];

    const int tid  = threadIdx.x;
    const int wid  = tid >> 5;
    const int lane = tid & 31;
    const int gid  = lane >> 2;     // 0..7
    const int tig  = lane & 3;      // 0..3
    const int pr   = wid >> 1;      // pair id 0/1
    const int j    = wid & 1;       // n-half within pair
    const int colbase = 32 * j;

    if (tid < JDIM) sKP[tid] = kpts[tid];

    // ---- one-time: stage W (aliased into sA), build this lane's fp16 B frags ----
    float* sWf = reinterpret_cast<float*>(&sA[0][0][0][0]);
    for (int i = tid; i < JDIM * COUT_; i += NTHR) sWf[i] = wts[i];
    __syncthreads();

    uint32_t B[4][3][2];
#pragma unroll
    for (int nt = 0; nt < 4; nt++) {
#pragma unroll
        for (int kt = 0; kt < 3; kt++) {
            int n  = colbase + nt * 8 + gid;
            int j0 = kt * 16 + 2 * tig;
#pragma unroll
            for (int h = 0; h < 2; h++) {
                float w0 = sWf[(j0 + 8 * h    ) * COUT_ + n];
                float w1 = sWf[(j0 + 8 * h + 1) * COUT_ + n];
                B[nt][kt][h] = pack_h_rn(w0, w1);
            }
        }
    }

    // ---- hoist my 8 kernel points into registers (off the exp critical path) ----
    const int kh = lane & 1;
    float kpx[8], kpy[8], kpz[8];
#pragma unroll
    for (int kk = 0; kk < 8; kk++) {
        kpx[kk] = sKP[3 * (8 * kh + kk) + 0];
        kpy[kk] = sKP[3 * (8 * kh + kk) + 1];
        kpz[kk] = sKP[3 * (8 * kh + kk) + 2];
    }
    __syncthreads();   // W staging dead; sA belongs to pairs now

    const float sg  = sigma[0];
    const float cc2 = -0.72134752f / (sg * sg);   // -0.5*log2(e)/sigma^2

    const uint32_t lmoff = (uint32_t)(lane & 15) * ROWB + (uint32_t)(lane >> 4) * 16;
    const uint32_t sbase = smem_u32(&sA[0][0][0][0]);

    const int ngroups = (npts + 31) >> 5;
    const int g0      = blockIdx.x * 2 + pr;
    const int gstep   = gridDim.x * 2;
    const int barid   = pr + 1;
    const int r       = lane >> 1;        // my staging row

    // ---- prefetch first group's x ----
    float xc0 = 0.f, xc1 = 0.f, xc2 = 0.f;
    {
        const int p = (g0 << 5) + j * 16 + r;
        if (g0 < ngroups && p < npts) { xc0 = x[3 * p]; xc1 = x[3 * p + 1]; xc2 = x[3 * p + 2]; }
    }

    int buf = 0;
    for (int grp = g0; grp < ngroups; grp += gstep, buf ^= 1) {
        const int rowbase = grp << 5;

        // ---- phase 1: build my 16-row tile from prefetched x ----
        {
            float a[24];
#pragma unroll
            for (int kk = 0; kk < 8; kk++) {
                float dx = xc0 - kpx[kk], dy = xc1 - kpy[kk], dz = xc2 - kpz[kk];
                float d2 = fmaf(dx, dx, fmaf(dy, dy, dz * dz));
                float g  = ex2f(cc2 * d2);
                a[3 * kk] = g * xc0; a[3 * kk + 1] = g * xc1; a[3 * kk + 2] = g * xc2;
            }
            uint32_t hv[12], lv[12];
#pragma unroll
            for (int m = 0; m < 12; m++) {
                float a0 = a[2 * m], a1 = a[2 * m + 1];
                uint32_t hp = pack_h_rn(a0, a1);
                __half2 h2 = *reinterpret_cast<__half2*>(&hp);
                hv[m] = hp;
                lv[m] = pack_h_rn(a0 - __low2float(h2), a1 - __high2float(h2));
            }
            char* rh = &sA[buf][wid][0][0] + r * ROWB + kh * 48;
            char* rl = &sA[buf][wid][1][0] + r * ROWB + kh * 48;
#pragma unroll
            for (int q = 0; q < 3; q++) {
                *reinterpret_cast<uint4*>(rh + q * 16) =
                    make_uint4(hv[4 * q], hv[4 * q + 1], hv[4 * q + 2], hv[4 * q + 3]);
                *reinterpret_cast<uint4*>(rl + q * 16) =
                    make_uint4(lv[4 * q], lv[4 * q + 1], lv[4 * q + 2], lv[4 * q + 3]);
            }
        }

        // ---- prefetch next group's x (overlaps bar + MMA + epilogue) ----
        xc0 = 0.f; xc1 = 0.f; xc2 = 0.f;
        {
            const int gn = grp + gstep;
            const int pn = (gn << 5) + j * 16 + r;
            if (gn < ngroups && pn < npts) {
                xc0 = x[3 * pn]; xc1 = x[3 * pn + 1]; xc2 = x[3 * pn + 2];
            }
        }

        bar_pair(barid);   // both tiles of this group ready

        // ---- phase 2: my 32-col n-half of both 16-row tiles, 2 passes ----
        float acc[2][4][4];
#pragma unroll
        for (int t = 0; t < 2; t++)
#pragma unroll
            for (int nt = 0; nt < 4; nt++)
#pragma unroll
                for (int c = 0; c < 4; c++) acc[t][nt][c] = 0.f;

#pragma unroll
        for (int t = 0; t < 2; t++) {
            const int ownerw = 2 * pr + t;
            const uint32_t aHi = sbase + ((uint32_t)(buf * 8 + ownerw * 2 + 0)) * AWARP + lmoff;
            const uint32_t aLo = sbase + ((uint32_t)(buf * 8 + ownerw * 2 + 1)) * AWARP + lmoff;
#pragma unroll
            for (int kt = 0; kt < 3; kt++) {
                uint32_t ah[4], al[4];
                ldsm_x4(ah, aHi + kt * 32);
                ldsm_x4(al, aLo + kt * 32);
#pragma unroll
                for (int nt = 0; nt < 4; nt++) mma_f16(acc[t][nt], ah, B[nt][kt]);
#pragma unroll
                for (int nt = 0; nt < 4; nt++) mma_f16(acc[t][nt], al, B[nt][kt]);
            }
        }

        // ---- epilogue: butterfly (xor 1) -> float4 -> STG.128 ----
        const bool ev = (tig & 1) == 0;
#pragma unroll
        for (int t = 0; t < 2; t++) {
            const int rowLo = rowbase + 16 * t + gid;
            const int rowHi = rowLo + 8;
#pragma unroll
            for (int ntp = 0; ntp < 2; ntp++) {
                const int ntA = 2 * ntp, ntB = ntA + 1;
                const int col = colbase +
                    (ev ? (16 * ntp + 2 * tig) : (16 * ntp + 8 + 2 * (tig - 1)));
#pragma unroll
                for (int hseg = 0; hseg < 2; hseg++) {
                    float m0 = acc[t][ntA][2 * hseg], m1 = acc[t][ntA][2 * hseg + 1];
                    float b0 = acc[t][ntB][2 * hseg], b1 = acc[t][ntB][2 * hseg + 1];
                    float s0 = ev ? b0 : m0;
                    float s1 = ev ? b1 : m1;
                    float r0 = __shfl_xor_sync(0xFFFFFFFFu, s0, 1);
                    float r1 = __shfl_xor_sync(0xFFFFFFFFu, s1, 1);
                    float4 v;
                    if (ev) v = make_float4(m0, m1, r0, r1);
                    else    v = make_float4(r0, r1, b0, b1);
                    const int row = hseg ? rowHi : rowLo;
                    if (row < npts)
                        *reinterpret_cast<float4*>(out + (size_t)row * COUT_ + col) = v;
                }
            }
        }
        // no second barrier: double buffering + next iteration's bar orders reuse
    }
}

extern "C" void kernel_launch(void* const* d_in, const int* in_sizes, int n_in,
                              void* d_out, int out_size)
{
    const float *x = nullptr, *kp = nullptr, *wt = nullptr, *sg = nullptr;
    int x_elems = 0;
    for (int i = 0; i < n_in; i++) {
        int s = in_sizes[i];
        if (s == 1)                    sg = (const float*)d_in[i];
        else if (s == JDIM)            kp = (const float*)d_in[i];
        else if (s == KP_ * 3 * COUT_) wt = (const float*)d_in[i];
        else { x = (const float*)d_in[i]; x_elems = s; }
    }
    const int npts    = x_elems / 3;
    const int ngroups = (npts + 31) >> 5;
    int grid = 148 * 5;
    int maxg = (ngroups + 1) / 2;
    if (grid > maxg) grid = maxg;

    kpconv_f16q_kernel<<<grid, NTHR>>>(x, kp, wt, sg, (float*)d_out, npts);
}

// round 13
// speedup vs baseline: 1.0656x; 1.0656x over previous
#include <cuda_runtime.h>
#include <cuda_fp16.h>
#include <cstdint>

// KPConv warp-MMA GEMM: R6 pair-split frame, SINGLE-PASS fp16 (A and W both
// rounded once to fp16; fp32 accum). rel_err budget ~3-5e-4 < 1e-3.
//   A[p, j] = exp(-0.5*d2(p,k)/sigma^2) * x[p,i]  (j=3k+i, 48 cols = 3 k-tiles)
//   out = A @ W.
// Pair of warps owns a 32-row group; each warp builds its 16-row fp16 A tile
// (stride 144B), computes its 32-col n-half of BOTH tiles. Double-buffered A;
// one named bar.sync(64)/iter; kernel points hoisted to registers.

#define KP_    16
#define JDIM   48
#define COUT_  64
#define NTHR   128
#define ROWB   144
#define AWARP  (16 * ROWB)   // 2304 B per warp tile

__device__ __forceinline__ uint32_t smem_u32(const void* p) {
    uint32_t a;
    asm("{ .reg .u64 t; cvta.to.shared.u64 t, %1; cvt.u32.u64 %0, t; }" : "=r"(a) : "l"(p));
    return a;
}
__device__ __forceinline__ uint32_t pack_h_rn(float lo, float hi) {
    uint32_t r;
    asm("cvt.rn.f16x2.f32 %0, %1, %2;" : "=r"(r) : "f"(hi), "f"(lo));
    return r;
}
__device__ __forceinline__ void ldsm_x4(uint32_t* r, uint32_t addr) {
    asm volatile("ldmatrix.sync.aligned.m8n8.x4.shared.b16 {%0,%1,%2,%3}, [%4];"
                 : "=r"(r[0]), "=r"(r[1]), "=r"(r[2]), "=r"(r[3]) : "r"(addr));
}
__device__ __forceinline__ void mma_f16(float* c, const uint32_t* a, const uint32_t* b) {
    asm volatile(
        "mma.sync.aligned.m16n8k16.row.col.f32.f16.f16.f32 "
        "{%0,%1,%2,%3}, {%4,%5,%6,%7}, {%8,%9}, {%0,%1,%2,%3};"
        : "+f"(c[0]), "+f"(c[1]), "+f"(c[2]), "+f"(c[3])
        : "r"(a[0]), "r"(a[1]), "r"(a[2]), "r"(a[3]), "r"(b[0]), "r"(b[1]));
}
__device__ __forceinline__ float ex2f(float a) {
    float r;
    asm("ex2.approx.f32 %0, %1;" : "=f"(r) : "f"(a));
    return r;
}
__device__ __forceinline__ void bar_pair(int id) {
    asm volatile("bar.sync %0, 64;" :: "r"(id) : "memory");
}

__global__ __launch_bounds__(NTHR, 5)
void kpconv_f16s_kernel(const float* __restrict__ x,
                        const float* __restrict__ kpts,
                        const float* __restrict__ wts,
                        const float* __restrict__ sigma,
                        float* __restrict__ out,
                        int npts)
{
    // [buf][warp][16 rows x 144B] = 18432 B; W (12288B) staged aliased.
    __shared__ __align__(16) char sA[2][4][AWARP];
    __shared__ float sKP[JDIM];

    const int tid  = threadIdx.x;
    const int wid  = tid >> 5;
    const int lane = tid & 31;
    const int gid  = lane >> 2;     // 0..7
    const int tig  = lane & 3;      // 0..3
    const int pr   = wid >> 1;      // pair id 0/1
    const int j    = wid & 1;       // n-half within pair
    const int colbase = 32 * j;

    if (tid < JDIM) sKP[tid] = kpts[tid];

    // ---- one-time: stage W (aliased into sA), build this lane's fp16 B frags ----
    float* sWf = reinterpret_cast<float*>(&sA[0][0][0]);
    for (int i = tid; i < JDIM * COUT_; i += NTHR) sWf[i] = wts[i];
    __syncthreads();

    uint32_t B[4][3][2];
#pragma unroll
    for (int nt = 0; nt < 4; nt++) {
#pragma unroll
        for (int kt = 0; kt < 3; kt++) {
            int n  = colbase + nt * 8 + gid;
            int j0 = kt * 16 + 2 * tig;
#pragma unroll
            for (int h = 0; h < 2; h++) {
                float w0 = sWf[(j0 + 8 * h    ) * COUT_ + n];
                float w1 = sWf[(j0 + 8 * h + 1) * COUT_ + n];
                B[nt][kt][h] = pack_h_rn(w0, w1);
            }
        }
    }

    // ---- hoist my 8 kernel points into registers ----
    const int kh = lane & 1;
    float kpx[8], kpy[8], kpz[8];
#pragma unroll
    for (int kk = 0; kk < 8; kk++) {
        kpx[kk] = sKP[3 * (8 * kh + kk) + 0];
        kpy[kk] = sKP[3 * (8 * kh + kk) + 1];
        kpz[kk] = sKP[3 * (8 * kh + kk) + 2];
    }
    __syncthreads();   // W staging dead; sA belongs to pairs now

    const float sg  = sigma[0];
    const float cc2 = -0.72134752f / (sg * sg);   // -0.5*log2(e)/sigma^2

    const uint32_t lmoff = (uint32_t)(lane & 15) * ROWB + (uint32_t)(lane >> 4) * 16;
    const uint32_t sbase = smem_u32(&sA[0][0][0]);

    const int ngroups = (npts + 31) >> 5;
    const int g0      = blockIdx.x * 2 + pr;
    const int gstep   = gridDim.x * 2;
    const int barid   = pr + 1;
    const int r       = lane >> 1;        // my staging row

    int buf = 0;
    for (int grp = g0; grp < ngroups; grp += gstep, buf ^= 1) {
        const int rowbase = grp << 5;

        // ---- phase 1: build my 16-row fp16 tile ----
        {
            const int p = rowbase + j * 16 + r;
            float x0 = 0.f, x1 = 0.f, x2 = 0.f;
            if (p < npts) { x0 = x[3 * p]; x1 = x[3 * p + 1]; x2 = x[3 * p + 2]; }
            float a[24];
#pragma unroll
            for (int kk = 0; kk < 8; kk++) {
                float dx = x0 - kpx[kk], dy = x1 - kpy[kk], dz = x2 - kpz[kk];
                float d2 = fmaf(dx, dx, fmaf(dy, dy, dz * dz));
                float g  = ex2f(cc2 * d2);
                a[3 * kk] = g * x0; a[3 * kk + 1] = g * x1; a[3 * kk + 2] = g * x2;
            }
            uint32_t hv[12];
#pragma unroll
            for (int m = 0; m < 12; m++)
                hv[m] = pack_h_rn(a[2 * m], a[2 * m + 1]);
            char* rh = &sA[buf][wid][0] + r * ROWB + kh * 48;
#pragma unroll
            for (int q = 0; q < 3; q++) {
                *reinterpret_cast<uint4*>(rh + q * 16) =
                    make_uint4(hv[4 * q], hv[4 * q + 1], hv[4 * q + 2], hv[4 * q + 3]);
            }
        }
        bar_pair(barid);   // both tiles of this group ready

        // ---- phase 2: my 32-col n-half of both 16-row tiles, single pass ----
        float acc[2][4][4];
#pragma unroll
        for (int t = 0; t < 2; t++)
#pragma unroll
            for (int nt = 0; nt < 4; nt++)
#pragma unroll
                for (int c = 0; c < 4; c++) acc[t][nt][c] = 0.f;

#pragma unroll
        for (int t = 0; t < 2; t++) {
            const int ownerw = 2 * pr + t;
            const uint32_t aBase = sbase + ((uint32_t)(buf * 4 + ownerw)) * AWARP + lmoff;
#pragma unroll
            for (int kt = 0; kt < 3; kt++) {
                uint32_t ah[4];
                ldsm_x4(ah, aBase + kt * 32);
#pragma unroll
                for (int nt = 0; nt < 4; nt++) mma_f16(acc[t][nt], ah, B[nt][kt]);
            }
        }

        // ---- epilogue: butterfly (xor 1) -> float4 -> STG.128 ----
        const bool ev = (tig & 1) == 0;
#pragma unroll
        for (int t = 0; t < 2; t++) {
            const int rowLo = rowbase + 16 * t + gid;
            const int rowHi = rowLo + 8;
#pragma unroll
            for (int ntp = 0; ntp < 2; ntp++) {
                const int ntA = 2 * ntp, ntB = ntA + 1;
                const int col = colbase +
                    (ev ? (16 * ntp + 2 * tig) : (16 * ntp + 8 + 2 * (tig - 1)));
#pragma unroll
                for (int hseg = 0; hseg < 2; hseg++) {
                    float m0 = acc[t][ntA][2 * hseg], m1 = acc[t][ntA][2 * hseg + 1];
                    float b0 = acc[t][ntB][2 * hseg], b1 = acc[t][ntB][2 * hseg + 1];
                    float s0 = ev ? b0 : m0;
                    float s1 = ev ? b1 : m1;
                    float r0 = __shfl_xor_sync(0xFFFFFFFFu, s0, 1);
                    float r1 = __shfl_xor_sync(0xFFFFFFFFu, s1, 1);
                    float4 v;
                    if (ev) v = make_float4(m0, m1, r0, r1);
                    else    v = make_float4(r0, r1, b0, b1);
                    const int row = hseg ? rowHi : rowLo;
                    if (row < npts)
                        *reinterpret_cast<float4*>(out + (size_t)row * COUT_ + col) = v;
                }
            }
        }
        // no second barrier: double buffering + next iteration's bar orders reuse
    }
}

extern "C" void kernel_launch(void* const* d_in, const int* in_sizes, int n_in,
                              void* d_out, int out_size)
{
    const float *x = nullptr, *kp = nullptr, *wt = nullptr, *sg = nullptr;
    int x_elems = 0;
    for (int i = 0; i < n_in; i++) {
        int s = in_sizes[i];
        if (s == 1)                    sg = (const float*)d_in[i];
        else if (s == JDIM)            kp = (const float*)d_in[i];
        else if (s == KP_ * 3 * COUT_) wt = (const float*)d_in[i];
        else { x = (const float*)d_in[i]; x_elems = s; }
    }
    const int npts    = x_elems / 3;
    const int ngroups = (npts + 31) >> 5;
    int grid = 148 * 5;
    int maxg = (ngroups + 1) / 2;
    if (grid > maxg) grid = maxg;

    kpconv_f16s_kernel<<<grid, NTHR>>>(x, kp, wt, sg, (float*)d_out, npts);
}

// round 15
// speedup vs baseline: 1.3547x; 1.2713x over previous
#include <cuda_runtime.h>
#include <cuda_fp16.h>
#include <cstdint>

// KPConv warp-MMA GEMM: pair-split single-pass fp16, SOFTWARE-PIPELINED:
// per iteration: ldsm(current) -> compute A(next) -> prefetch x(next+1)
// -> MMA(current) -> STG -> bar.  Double-buffered A staging.
//   A[p, j] = exp(-0.5*d2(p,k)/sigma^2) * x[p,i]  (j=3k+i, 48 cols, 3 k-tiles)
//   out = A @ W   (both rounded once to fp16, fp32 accum; rel_err ~2.9e-4)

#define KP_    16
#define JDIM   48
#define COUT_  64
#define NTHR   128
#define ROWB   144
#define AWARP  (16 * ROWB)   // 2304 B per warp tile

__device__ __forceinline__ uint32_t smem_u32(const void* p) {
    uint32_t a;
    asm("{ .reg .u64 t; cvta.to.shared.u64 t, %1; cvt.u32.u64 %0, t; }" : "=r"(a) : "l"(p));
    return a;
}
__device__ __forceinline__ uint32_t pack_h_rn(float lo, float hi) {
    uint32_t r;
    asm("cvt.rn.f16x2.f32 %0, %1, %2;" : "=r"(r) : "f"(hi), "f"(lo));
    return r;
}
__device__ __forceinline__ void ldsm_x4(uint32_t* r, uint32_t addr) {
    asm volatile("ldmatrix.sync.aligned.m8n8.x4.shared.b16 {%0,%1,%2,%3}, [%4];"
                 : "=r"(r[0]), "=r"(r[1]), "=r"(r[2]), "=r"(r[3]) : "r"(addr));
}
__device__ __forceinline__ void mma_f16(float* c, const uint32_t* a, const uint32_t* b) {
    asm volatile(
        "mma.sync.aligned.m16n8k16.row.col.f32.f16.f16.f32 "
        "{%0,%1,%2,%3}, {%4,%5,%6,%7}, {%8,%9}, {%0,%1,%2,%3};"
        : "+f"(c[0]), "+f"(c[1]), "+f"(c[2]), "+f"(c[3])
        : "r"(a[0]), "r"(a[1]), "r"(a[2]), "r"(a[3]), "r"(b[0]), "r"(b[1]));
}
__device__ __forceinline__ float ex2f(float a) {
    float r;
    asm("ex2.approx.f32 %0, %1;" : "=f"(r) : "f"(a));
    return r;
}
__device__ __forceinline__ void bar_pair(int id) {
    asm volatile("bar.sync %0, 64;" :: "r"(id) : "memory");
}

__global__ __launch_bounds__(NTHR, 4)
void kpconv_pipe_kernel(const float* __restrict__ x,
                        const float* __restrict__ kpts,
                        const float* __restrict__ wts,
                        const float* __restrict__ sigma,
                        float* __restrict__ out,
                        int npts)
{
    // [buf][warp][16 rows x 144B] = 18432 B; W (12288B) staged aliased.
    __shared__ __align__(16) char sA[2][4][AWARP];
    __shared__ float4 sKP4[KP_];

    const int tid  = threadIdx.x;
    const int wid  = tid >> 5;
    const int lane = tid & 31;
    const int gid  = lane >> 2;     // 0..7
    const int tig  = lane & 3;      // 0..3
    const int pr   = wid >> 1;      // pair id 0/1
    const int j    = wid & 1;       // n-half within pair
    const int colbase = 32 * j;

    if (tid < KP_)
        sKP4[tid] = make_float4(kpts[3 * tid], kpts[3 * tid + 1], kpts[3 * tid + 2], 0.f);

    // ---- one-time: stage W (aliased into sA), build this lane's fp16 B frags ----
    float* sWf = reinterpret_cast<float*>(&sA[0][0][0]);
    for (int i = tid; i < JDIM * COUT_; i += NTHR) sWf[i] = wts[i];
    __syncthreads();

    uint32_t B[4][3][2];
#pragma unroll
    for (int nt = 0; nt < 4; nt++) {
#pragma unroll
        for (int kt = 0; kt < 3; kt++) {
            int n  = colbase + nt * 8 + gid;
            int j0 = kt * 16 + 2 * tig;
#pragma unroll
            for (int h = 0; h < 2; h++) {
                float w0 = sWf[(j0 + 8 * h    ) * COUT_ + n];
                float w1 = sWf[(j0 + 8 * h + 1) * COUT_ + n];
                B[nt][kt][h] = pack_h_rn(w0, w1);
            }
        }
    }
    __syncthreads();   // W staging dead; sA belongs to pairs now

    const float sg  = sigma[0];
    const float cc2 = -0.72134752f / (sg * sg);   // -0.5*log2(e)/sigma^2

    const uint32_t lmoff = (uint32_t)(lane & 15) * ROWB + (uint32_t)(lane >> 4) * 16;
    const uint32_t sbase = smem_u32(&sA[0][0][0]);

    const int ngroups = (npts + 31) >> 5;
    const int g0      = blockIdx.x * 2 + pr;
    const int gstep   = gridDim.x * 2;
    const int barid   = pr + 1;
    const int r       = lane >> 1;        // my staging row
    const int kh      = lane & 1;         // my k-half

    // phase-1 A-tile builder (writes sA[b][wid] from x-coords in regs)
    auto build_A = [&](int b, float x0, float x1, float x2) {
        float a[24];
#pragma unroll
        for (int kk = 0; kk < 8; kk++) {
            const float4 kp = sKP4[8 * kh + kk];
            float dx = x0 - kp.x, dy = x1 - kp.y, dz = x2 - kp.z;
            float d2 = fmaf(dx, dx, fmaf(dy, dy, dz * dz));
            float g  = ex2f(cc2 * d2);
            a[3 * kk] = g * x0; a[3 * kk + 1] = g * x1; a[3 * kk + 2] = g * x2;
        }
        uint32_t hv[12];
#pragma unroll
        for (int m = 0; m < 12; m++)
            hv[m] = pack_h_rn(a[2 * m], a[2 * m + 1]);
        char* rh = &sA[b][wid][0] + r * ROWB + kh * 48;
#pragma unroll
        for (int q = 0; q < 3; q++)
            *reinterpret_cast<uint4*>(rh + q * 16) =
                make_uint4(hv[4 * q], hv[4 * q + 1], hv[4 * q + 2], hv[4 * q + 3]);
    };
    auto load_x = [&](int g, float& x0, float& x1, float& x2) {
        x0 = 0.f; x1 = 0.f; x2 = 0.f;
        if (g < ngroups) {
            const int p = (g << 5) + j * 16 + r;
            if (p < npts) { x0 = x[3 * p]; x1 = x[3 * p + 1]; x2 = x[3 * p + 2]; }
        }
    };

    // ---- prologue: A(g0) into buf0; prefetch x(g0+gstep) ----
    if (g0 < ngroups) {
        float x0, x1, x2;
        load_x(g0, x0, x1, x2);
        build_A(0, x0, x1, x2);
    }
    float xn0, xn1, xn2;
    load_x(g0 + gstep, xn0, xn1, xn2);
    bar_pair(barid);

    int buf = 0;
    for (int grp = g0; grp < ngroups; grp += gstep, buf ^= 1) {
        const int rowbase = grp << 5;

        // ---- (1) issue ldsm for current group's two tiles (buf is ready) ----
        uint32_t ah[2][3][4];
#pragma unroll
        for (int t = 0; t < 2; t++) {
            const uint32_t aBase = sbase + ((uint32_t)(buf * 4 + 2 * pr + t)) * AWARP + lmoff;
#pragma unroll
            for (int kt = 0; kt < 3; kt++)
                ldsm_x4(ah[t][kt], aBase + kt * 32);
        }

        // ---- (2) build next group's A tile into buf^1 (fills ldsm latency) ----
        if (grp + gstep < ngroups)
            build_A(buf ^ 1, xn0, xn1, xn2);

        // ---- (3) prefetch x two groups ahead ----
        load_x(grp + 2 * gstep, xn0, xn1, xn2);

        // ---- (4) MMA current group ----
        float acc[2][4][4];
#pragma unroll
        for (int t = 0; t < 2; t++)
#pragma unroll
            for (int nt = 0; nt < 4; nt++)
#pragma unroll
                for (int c = 0; c < 4; c++) acc[t][nt][c] = 0.f;
#pragma unroll
        for (int t = 0; t < 2; t++)
#pragma unroll
            for (int kt = 0; kt < 3; kt++)
#pragma unroll
                for (int nt = 0; nt < 4; nt++)
                    mma_f16(acc[t][nt], ah[t][kt], B[nt][kt]);

        // ---- epilogue: butterfly (xor 1) -> float4 -> STG.128 ----
        const bool ev = (tig & 1) == 0;
#pragma unroll
        for (int t = 0; t < 2; t++) {
            const int rowLo = rowbase + 16 * t + gid;
            const int rowHi = rowLo + 8;
#pragma unroll
            for (int ntp = 0; ntp < 2; ntp++) {
                const int ntA = 2 * ntp, ntB = ntA + 1;
                const int col = colbase +
                    (ev ? (16 * ntp + 2 * tig) : (16 * ntp + 8 + 2 * (tig - 1)));
#pragma unroll
                for (int hseg = 0; hseg < 2; hseg++) {
                    float m0 = acc[t][ntA][2 * hseg], m1 = acc[t][ntA][2 * hseg + 1];
                    float b0 = acc[t][ntB][2 * hseg], b1 = acc[t][ntB][2 * hseg + 1];
                    float s0 = ev ? b0 : m0;
                    float s1 = ev ? b1 : m1;
                    float r0 = __shfl_xor_sync(0xFFFFFFFFu, s0, 1);
                    float r1 = __shfl_xor_sync(0xFFFFFFFFu, s1, 1);
                    float4 v;
                    if (ev) v = make_float4(m0, m1, r0, r1);
                    else    v = make_float4(r0, r1, b0, b1);
                    const int row = hseg ? rowHi : rowLo;
                    if (row < npts)
                        *reinterpret_cast<float4*>(out + (size_t)row * COUT_ + col) = v;
                }
            }
        }

        // ---- (5) one barrier: next group's A (both warps) complete ----
        bar_pair(barid);
    }
}

extern "C" void kernel_launch(void* const* d_in, const int* in_sizes, int n_in,
                              void* d_out, int out_size)
{
    const float *x = nullptr, *kp = nullptr, *wt = nullptr, *sg = nullptr;
    int x_elems = 0;
    for (int i = 0; i < n_in; i++) {
        int s = in_sizes[i];
        if (s == 1)                    sg = (const float*)d_in[i];
        else if (s == JDIM)            kp = (const float*)d_in[i];
        else if (s == KP_ * 3 * COUT_) wt = (const float*)d_in[i];
        else { x = (const float*)d_in[i]; x_elems = s; }
    }
    const int npts    = x_elems / 3;
    const int ngroups = (npts + 31) >> 5;
    int grid = 148 * 4;
    int maxg = (ngroups + 1) / 2;
    if (grid > maxg) grid = maxg;

    kpconv_pipe_kernel<<<grid, NTHR>>>(x, kp, wt, sg, (float*)d_out, npts);
}